// round 14
// baseline (speedup 1.0000x reference)
#include <cuda_runtime.h>
#include <cuda_fp16.h>
#include <math.h>
#include <stdint.h>

// Problem constants: B=64, N=1024, D=8, S=16 -> DS=128, K=1024
#define NN    1024
#define BB    64
#define DS    128
#define KDIM  1024
#define NKB   (KDIM / 16)            // 64 k16-blocks
#define NSTG  8                      // pipeline stages
#define STGB  8192                   // bytes per stage: A 4KB + B 4KB (frag order)
#define C_STRIDE 129
#define SMEM_REQ (128 * C_STRIDE * 4 + 1024)   // 67072 (covers 1024 + 8*8192 = 66560)

__device__ __forceinline__ uint32_t smem_u32(const void* p) {
    uint32_t a;
    asm("{ .reg .u64 t; cvta.to.shared.u64 t, %1; cvt.u32.u64 %0, t; }" : "=r"(a) : "l"(p));
    return a;
}
__device__ __forceinline__ void cp16(uint32_t dst, const void* src) {
    asm volatile("cp.async.cg.shared.global [%0], [%1], 16;" :: "r"(dst), "l"(src) : "memory");
}
__device__ __forceinline__ void mma16816(float* c, const uint32_t* a, uint32_t b0, uint32_t b1) {
    asm volatile("mma.sync.aligned.m16n8k16.row.col.f32.f16.f16.f32 "
                 "{%0,%1,%2,%3}, {%4,%5,%6,%7}, {%8,%9}, {%0,%1,%2,%3};"
                 : "+f"(c[0]), "+f"(c[1]), "+f"(c[2]), "+f"(c[3])
                 : "r"(a[0]), "r"(a[1]), "r"(a[2]), "r"(a[3]), "r"(b0), "r"(b1));
}

#define MB_INIT(mbar, cnt) \
    asm volatile("mbarrier.init.shared.b64 [%0], %1;" :: "r"(mbar), "r"((uint32_t)(cnt)) : "memory")
#define MB_ARRIVE(mbar) \
    asm volatile("mbarrier.arrive.shared.b64 _, [%0];" :: "r"(mbar) : "memory")
// .noinc is load-bearing: without it each call bumps the pending count first
// (net-zero progress) and the barrier never completes (R11 deadlock).
#define CP_MB_ARRIVE(mbar) \
    asm volatile("cp.async.mbarrier.arrive.noinc.shared::cta.b64 [%0];" :: "r"(mbar) : "memory")
#define MB_WAIT(mbar, par) do {                                                \
    uint32_t _m = (mbar); uint32_t _p = (uint32_t)(par);                       \
    asm volatile("{\n\t.reg .pred P1;\n\t"                                     \
        "WL_%=:\n\t"                                                           \
        "mbarrier.try_wait.parity.acquire.cta.shared::cta.b64 P1, [%0], %1, 0x989680;\n\t" \
        "@P1 bra.uni WD_%=;\n\t"                                               \
        "bra.uni WL_%=;\n\t"                                                   \
        "WD_%=:\n\t}"                                                          \
        :: "r"(_m), "r"(_p) : "memory");                                       \
} while (0)

// ---------------- device scratch: FRAGMENT-ORDERED operands ----------------
// A frags: [row16 0..63][kb 0..63][lane 0..31][4 u32]   (2 MB)
// B frags: [b*8 + n16][kb][lane][4 u32]                (16 MB)
__device__ uint32_t g_Af[64 * NKB * 128];
__device__ uint32_t g_Xf[BB * 8 * NKB * 128];

// ---------------- prep: build fragment-ordered A and B (proven R10) --------
__global__ void prep(const float* __restrict__ x, const float* __restrict__ M)
{
    const int tid = threadIdx.x;
    const int kb  = blockIdx.x;

    if (tid < 128) {
        const int row16 = blockIdx.y;
        const int lane = tid >> 2, reg = tid & 3;
        const int R = row16 * 16 + (lane >> 2) + (reg & 1) * 8;
        const int C = kb * 16 + (lane & 3) * 2 + ((reg >> 1) & 1) * 8;
        const float2 mv = *(const float2*)&M[(size_t)R * NN + C];
        const __half2 h = __floats2half2_rn(mv.x, mv.y);
        g_Af[((size_t)row16 * NKB + kb) * 128 + tid] = *(const uint32_t*)&h;
    }

    __shared__ float sx[16 * 132];
    const int b = blockIdx.y;
    const float* src = x + ((size_t)b * NN + kb * 16) * DS;
#pragma unroll
    for (int j = tid; j < 16 * 128; j += 256) {
        const int r = j >> 7, c = j & 127;
        sx[r * 132 + c] = src[r * DS + c];
    }
    __syncthreads();

    uint32_t* dstB = g_Xf + ((size_t)(b * 8) * NKB + kb) * 128;
#pragma unroll
    for (int it = 0; it < 4; it++) {
        const int u = it * 256 + tid;
        const int n16 = u >> 7, tt = u & 127;
        const int lane = tt >> 2, reg = tt & 3;
        const int n  = n16 * 16 + (lane >> 2) + ((reg >> 1) & 1) * 8;
        const int k0 = (lane & 3) * 2 + (reg & 1) * 8;
        const __half2 h = __floats2half2_rn(sx[k0 * 132 + n], sx[(k0 + 1) * 132 + n]);
        dstB[(size_t)n16 * (NKB * 128) + tt] = *(const uint32_t*)&h;
    }
}

// ---------------- GEMM: 8-stage ring + SW-pipelined consumer ---------------
// Grid (8, 64). Block 256 = 8 warps (2 m x 4 n), warp m64n32.
// Consumer per kb: 8 MMAs(buf) -> wait full[kb+1] -> LDS kb+1(other buf)
//                  -> 8 MMAs(buf) -> arrive empty[kb].
__global__ void __launch_bounds__(256, 2) gemm_neuron(
    const float* __restrict__ w_syn,    // [N, 128]
    const float* __restrict__ b_dend,   // [N, 8]
    const float* __restrict__ w_dend,   // [N, 8]
    const float* __restrict__ b_soma,   // [N]
    float* __restrict__ out)            // [B, N]
{
    extern __shared__ char smem[];
    const uint32_t sb = smem_u32(smem);
    const int tid  = threadIdx.x;
    const int wid  = tid >> 5, lane = tid & 31;
    const int wm   = wid & 1;           // m-warp: 64 rows
    const int wn   = wid >> 1;          // n-warp: 32 cols
    const int o0   = blockIdx.x * 128;
    const int b    = blockIdx.y;

    if (tid == 0) {
#pragma unroll
        for (int s = 0; s < NSTG; s++) {
            MB_INIT(sb + s * 16,     256);   // full: 256 cp.async noinc arrivals
            MB_INIT(sb + s * 16 + 8, 8);     // empty: one arrive per warp
        }
    }
    __syncthreads();

    // staging role: threads 0..127 -> A tile (tt>>4), 128..255 -> B tile
    const int  isA = (tid < 128);
    const int  tt  = isA ? tid : tid - 128;
    const int  tile = isA ? (blockIdx.x * 8 + (tt >> 4)) : (b * 8 + (tt >> 4));
    const uint32_t* srcbase = (isA ? g_Af : g_Xf)
                            + ((size_t)tile * NKB) * 128 + (tt & 15) * 8;
    const uint32_t dstoff = 1024 + (isA ? 0 : 4096) + (tt >> 4) * 512 + (tt & 15) * 32;

#define STAGE(j, dowait) do {                                              \
    const int _s = (j) & (NSTG - 1);                                       \
    if (dowait) MB_WAIT(sb + _s * 16 + 8, (((j) >> 3) + 1) & 1);           \
    const uint32_t _d = sb + dstoff + _s * STGB;                           \
    const uint32_t* _src = srcbase + (size_t)(j) * 128;                    \
    cp16(_d,      _src);                                                   \
    cp16(_d + 16, _src + 4);                                               \
    CP_MB_ARRIVE(sb + _s * 16);                                            \
} while (0)

    // prologue: fill stages 0..6 (no waits needed, buffers virgin)
#pragma unroll
    for (int j = 0; j < NSTG - 1; j++) STAGE(j, false);

    float acc[4][4][4];
#pragma unroll
    for (int mt = 0; mt < 4; mt++)
#pragma unroll
        for (int nt = 0; nt < 4; nt++)
#pragma unroll
            for (int q = 0; q < 4; q++) acc[mt][nt][q] = 0.f;

    const uint32_t aoff = 1024 + wm * 4 * 512 + lane * 16;
    const uint32_t boff = 1024 + 4096 + wn * 2 * 512 + lane * 16;

#define LDFRAGS(Ar, Br, kb_) do {                                          \
    const char* _stg = smem + ((kb_) & (NSTG - 1)) * STGB;                 \
    _Pragma("unroll")                                                      \
    for (int mt = 0; mt < 4; mt++)                                         \
        Ar[mt] = *(const uint4*)(_stg + aoff + mt * 512);                  \
    _Pragma("unroll")                                                      \
    for (int bt = 0; bt < 2; bt++)                                         \
        Br[bt] = *(const uint4*)(_stg + boff + bt * 512);                  \
} while (0)

#define DOMMA_H(Ar, Br, mt0) do {                                          \
    _Pragma("unroll")                                                      \
    for (int mt = (mt0); mt < (mt0) + 2; mt++)                             \
        _Pragma("unroll")                                                  \
        for (int bt = 0; bt < 2; bt++) {                                   \
            mma16816(acc[mt][bt * 2],     (const uint32_t*)&Ar[mt],        \
                     Br[bt].x, Br[bt].y);                                  \
            mma16816(acc[mt][bt * 2 + 1], (const uint32_t*)&Ar[mt],        \
                     Br[bt].z, Br[bt].w);                                  \
        }                                                                  \
} while (0)

    uint4 A0[4], B0[2], A1[4], B1[2];

    // consumer prologue: stage 0 full -> load into buf0
    MB_WAIT(sb + 0 * 16, 0);
    LDFRAGS(A0, B0, 0);

#pragma unroll 1
    for (int kb = 0; kb < NKB; kb += 2) {
        // ---- half 1: consume buf0 (kb), prefetch kb+1 -> buf1 ----
        if (kb + 7 < NKB) STAGE(kb + 7, (kb + 7) >= NSTG);
        DOMMA_H(A0, B0, 0);
        MB_WAIT(sb + ((kb + 1) & (NSTG - 1)) * 16, ((kb + 1) >> 3) & 1);
        LDFRAGS(A1, B1, kb + 1);
        DOMMA_H(A0, B0, 2);
        if (lane == 0) MB_ARRIVE(sb + (kb & (NSTG - 1)) * 16 + 8);

        // ---- half 2: consume buf1 (kb+1), prefetch kb+2 -> buf0 ----
        if (kb + 8 < NKB) STAGE(kb + 8, true);
        DOMMA_H(A1, B1, 0);
        if (kb + 2 < NKB) {
            MB_WAIT(sb + ((kb + 2) & (NSTG - 1)) * 16, ((kb + 2) >> 3) & 1);
            LDFRAGS(A0, B0, kb + 2);
        }
        DOMMA_H(A1, B1, 2);
        if (lane == 0) MB_ARRIVE(sb + ((kb + 1) & (NSTG - 1)) * 16 + 8);
    }

    __syncthreads();   // protect mbarriers/stages before C overlay

    // ---- epilogue: frags -> C[128][129] fp32, then fused neuron math ----
    float* C = (float*)smem;
#pragma unroll
    for (int mt = 0; mt < 4; mt++)
#pragma unroll
        for (int nt = 0; nt < 4; nt++) {
            const int r  = wm * 64 + mt * 16 + (lane >> 2);
            const int cc = wn * 32 + nt * 8 + (lane & 3) * 2;
            C[r * C_STRIDE + cc]           = acc[mt][nt][0];
            C[r * C_STRIDE + cc + 1]       = acc[mt][nt][1];
            C[(r + 8) * C_STRIDE + cc]     = acc[mt][nt][2];
            C[(r + 8) * C_STRIDE + cc + 1] = acc[mt][nt][3];
        }
    __syncthreads();

    // 2 threads per o-row: (row, half h of ds)
    const int row = tid & 127;
    const int h   = tid >> 7;
    const int o   = o0 + row;
    float td[4] = {0.f, 0.f, 0.f, 0.f};
    const float4* w4 = (const float4*)(w_syn + (size_t)o * 128 + h * 64);
#pragma unroll
    for (int j4 = 0; j4 < 16; j4++) {
        const float4 w = w4[j4];
        const int e = h * 64 + j4 * 4;
        td[j4 >> 2] += C[row * C_STRIDE + e]     * w.x
                     + C[row * C_STRIDE + e + 1] * w.y
                     + C[row * C_STRIDE + e + 2] * w.z
                     + C[row * C_STRIDE + e + 3] * w.w;
    }
    float sh = 0.f;
#pragma unroll
    for (int d = 0; d < 4; d++) {
        const int dd = h * 4 + d;
        sh += tanhf(td[d] + b_dend[o * 8 + dd]) * w_dend[o * 8 + dd];
    }
    float* spart = (float*)(smem + 128 * C_STRIDE * 4);
    spart[h * 128 + row] = sh;
    __syncthreads();
    if (tid < 128) {
        const float s = spart[tid] + spart[128 + tid] + b_soma[o0 + tid];
        out[b * NN + o0 + tid] = 1.0f / (1.0f + expf(-s));
    }
}

// ---------------------------------------------------------------------------
extern "C" void kernel_launch(void* const* d_in, const int* in_sizes, int n_in,
                              void* d_out, int out_size)
{
    const float* x      = (const float*)d_in[0];   // [B, N, D, S]
    const float* M      = (const float*)d_in[1];   // [N, N]
    const float* w_syn  = (const float*)d_in[2];   // [N, D, S]
    const float* b_dend = (const float*)d_in[3];   // [N, D]
    const float* w_dend = (const float*)d_in[4];   // [N, D]
    const float* b_soma = (const float*)d_in[5];   // [N]
    float* out          = (float*)d_out;           // [B, N]

    cudaFuncSetAttribute(gemm_neuron, cudaFuncAttributeMaxDynamicSharedMemorySize, SMEM_REQ);

    prep<<<dim3(64, 64), 256>>>(x, M);
    gemm_neuron<<<dim3(NN / 128, BB), 256, SMEM_REQ>>>(w_syn, b_dend, w_dend, b_soma, out);
}

// round 15
// speedup vs baseline: 1.0302x; 1.0302x over previous
#include <cuda_runtime.h>
#include <cuda_fp16.h>
#include <math.h>
#include <stdint.h>

// Problem constants: B=64, N=1024, D=8, S=16 -> DS=128, K=1024
#define NN    1024
#define BB    64
#define DS    128
#define KDIM  1024
#define NKB   (KDIM / 16)            // 64 k16-blocks
#define NSTG  8                      // pipeline stages (B only)
#define STGB  4096                   // bytes per stage: B frags, 8 n16-tiles x 512B
#define C_STRIDE 129
#define SMEM_REQ (128 * C_STRIDE * 4 + 1024)   // 67072 (covers 1024 + 8*4096 = 33792)

__device__ __forceinline__ uint32_t smem_u32(const void* p) {
    uint32_t a;
    asm("{ .reg .u64 t; cvta.to.shared.u64 t, %1; cvt.u32.u64 %0, t; }" : "=r"(a) : "l"(p));
    return a;
}
__device__ __forceinline__ void cp16(uint32_t dst, const void* src) {
    asm volatile("cp.async.cg.shared.global [%0], [%1], 16;" :: "r"(dst), "l"(src) : "memory");
}
__device__ __forceinline__ void mma16816(float* c, const uint32_t* a, uint32_t b0, uint32_t b1) {
    asm volatile("mma.sync.aligned.m16n8k16.row.col.f32.f16.f16.f32 "
                 "{%0,%1,%2,%3}, {%4,%5,%6,%7}, {%8,%9}, {%0,%1,%2,%3};"
                 : "+f"(c[0]), "+f"(c[1]), "+f"(c[2]), "+f"(c[3])
                 : "r"(a[0]), "r"(a[1]), "r"(a[2]), "r"(a[3]), "r"(b0), "r"(b1));
}

#define MB_INIT(mbar, cnt) \
    asm volatile("mbarrier.init.shared.b64 [%0], %1;" :: "r"(mbar), "r"((uint32_t)(cnt)) : "memory")
#define MB_ARRIVE(mbar) \
    asm volatile("mbarrier.arrive.shared.b64 _, [%0];" :: "r"(mbar) : "memory")
// .noinc is load-bearing (R11 deadlock without it).
#define CP_MB_ARRIVE(mbar) \
    asm volatile("cp.async.mbarrier.arrive.noinc.shared::cta.b64 [%0];" :: "r"(mbar) : "memory")
#define MB_WAIT(mbar, par) do {                                                \
    uint32_t _m = (mbar); uint32_t _p = (uint32_t)(par);                       \
    asm volatile("{\n\t.reg .pred P1;\n\t"                                     \
        "WL_%=:\n\t"                                                           \
        "mbarrier.try_wait.parity.acquire.cta.shared::cta.b64 P1, [%0], %1, 0x989680;\n\t" \
        "@P1 bra.uni WD_%=;\n\t"                                               \
        "bra.uni WL_%=;\n\t"                                                   \
        "WD_%=:\n\t}"                                                          \
        :: "r"(_m), "r"(_p) : "memory");                                       \
} while (0)

// ---------------- device scratch: FRAGMENT-ORDERED operands ----------------
// A frags: [row16 0..63][kb 0..63][lane 0..31][4 u32]   (2 MB)
// B frags: [b*8 + n16][kb][lane][4 u32]                (16 MB)
__device__ uint32_t g_Af[64 * NKB * 128];
__device__ uint32_t g_Xf[BB * 8 * NKB * 128];

// ---------------- prep: build fragment-ordered A and B (proven R10) --------
__global__ void prep(const float* __restrict__ x, const float* __restrict__ M)
{
    const int tid = threadIdx.x;
    const int kb  = blockIdx.x;

    if (tid < 128) {
        const int row16 = blockIdx.y;
        const int lane = tid >> 2, reg = tid & 3;
        const int R = row16 * 16 + (lane >> 2) + (reg & 1) * 8;
        const int C = kb * 16 + (lane & 3) * 2 + ((reg >> 1) & 1) * 8;
        const float2 mv = *(const float2*)&M[(size_t)R * NN + C];
        const __half2 h = __floats2half2_rn(mv.x, mv.y);
        g_Af[((size_t)row16 * NKB + kb) * 128 + tid] = *(const uint32_t*)&h;
    }

    __shared__ float sx[16 * 132];
    const int b = blockIdx.y;
    const float* src = x + ((size_t)b * NN + kb * 16) * DS;
#pragma unroll
    for (int j = tid; j < 16 * 128; j += 256) {
        const int r = j >> 7, c = j & 127;
        sx[r * 132 + c] = src[r * DS + c];
    }
    __syncthreads();

    uint32_t* dstB = g_Xf + ((size_t)(b * 8) * NKB + kb) * 128;
#pragma unroll
    for (int it = 0; it < 4; it++) {
        const int u = it * 256 + tid;
        const int n16 = u >> 7, tt = u & 127;
        const int lane = tt >> 2, reg = tt & 3;
        const int n  = n16 * 16 + (lane >> 2) + ((reg >> 1) & 1) * 8;
        const int k0 = (lane & 3) * 2 + (reg & 1) * 8;
        const __half2 h = __floats2half2_rn(sx[k0 * 132 + n], sx[(k0 + 1) * 132 + n]);
        dstB[(size_t)n16 * (NKB * 128) + tt] = *(const uint32_t*)&h;
    }
}

// ---------------- GEMM: B-only smem ring + A register-prefetched LDG -------
// Grid (8, 64). Block 256 = 8 warps (2 m x 4 n), warp m64n32.
__global__ void __launch_bounds__(256, 2) gemm_neuron(
    const float* __restrict__ w_syn,    // [N, 128]
    const float* __restrict__ b_dend,   // [N, 8]
    const float* __restrict__ w_dend,   // [N, 8]
    const float* __restrict__ b_soma,   // [N]
    float* __restrict__ out)            // [B, N]
{
    extern __shared__ char smem[];
    const uint32_t sb = smem_u32(smem);
    const int tid  = threadIdx.x;
    const int wid  = tid >> 5, lane = tid & 31;
    const int wm   = wid & 1;           // m-warp: 64 rows
    const int wn   = wid >> 1;          // n-warp: 32 cols (n16 tiles wn*2, wn*2+1)
    const int o0   = blockIdx.x * 128;
    const int b    = blockIdx.y;

    if (tid == 0) {
#pragma unroll
        for (int s = 0; s < NSTG; s++) {
            MB_INIT(sb + s * 16,     256);   // full: 256 cp.async noinc arrivals
            MB_INIT(sb + s * 16 + 8, 8);     // empty: one arrive per warp
        }
    }
    __syncthreads();

    // B staging: thread tid owns 16B of each stage (n16 = tid>>5)
    const uint32_t* srcB = g_Xf + ((size_t)(b * 8 + (tid >> 5)) * NKB) * 128 + (tid & 31) * 4;
    const uint32_t dstoff = 1024 + (tid >> 5) * 512 + (tid & 31) * 16;

#define STAGE(j, dowait) do {                                              \
    const int _s = (j) & (NSTG - 1);                                       \
    if (dowait) MB_WAIT(sb + _s * 16 + 8, (((j) >> 3) + 1) & 1);           \
    cp16(sb + dstoff + _s * STGB, srcB + (size_t)(j) * 128);               \
    CP_MB_ARRIVE(sb + _s * 16);                                            \
} while (0)

    // prologue: fill stages 0..6 (buffers virgin, no waits)
#pragma unroll
    for (int j = 0; j < NSTG - 1; j++) STAGE(j, false);

    float acc[4][4][4];
#pragma unroll
    for (int mt = 0; mt < 4; mt++)
#pragma unroll
        for (int nt = 0; nt < 4; nt++)
#pragma unroll
            for (int q = 0; q < 4; q++) acc[mt][nt][q] = 0.f;

    // A fragments via direct LDG (L1-served: 4 n-warps issue identical addrs)
    const uint4* pa = (const uint4*)g_Af
                    + ((size_t)(blockIdx.x * 8 + wm * 4) * NKB) * 32 + lane;
    const uint32_t boff = 1024 + wn * 1024 + lane * 16;

#define LDGA(Ar, kb_) do {                                                 \
    _Pragma("unroll")                                                      \
    for (int mt = 0; mt < 4; mt++) Ar[mt] = pa[mt * 2048 + (kb_) * 32];    \
} while (0)

#define LDB(Br, kb_) do {                                                  \
    const char* _stg = smem + ((kb_) & (NSTG - 1)) * STGB;                 \
    Br[0] = *(const uint4*)(_stg + boff);                                  \
    Br[1] = *(const uint4*)(_stg + boff + 512);                            \
} while (0)

#define DOMMA(Ar, Br) do {                                                 \
    _Pragma("unroll")                                                      \
    for (int mt = 0; mt < 4; mt++)                                         \
        _Pragma("unroll")                                                  \
        for (int bt = 0; bt < 2; bt++) {                                   \
            mma16816(acc[mt][bt * 2],     (const uint32_t*)&Ar[mt],        \
                     Br[bt].x, Br[bt].y);                                  \
            mma16816(acc[mt][bt * 2 + 1], (const uint32_t*)&Ar[mt],        \
                     Br[bt].z, Br[bt].w);                                  \
        }                                                                  \
} while (0)

    uint4 A0[4], A1[4], Bf[2];
    LDGA(A0, 0);

#pragma unroll 1
    for (int kb = 0; kb < NKB; kb += 2) {
        // ---- even: consume kb with A0; prefetch A(kb+1) ----
        if (kb + 7 < NKB) STAGE(kb + 7, (kb + 7) >= NSTG);
        LDGA(A1, kb + 1);
        MB_WAIT(sb + (kb & (NSTG - 1)) * 16, (kb >> 3) & 1);
        LDB(Bf, kb);
        DOMMA(A0, Bf);
        if (lane == 0) MB_ARRIVE(sb + (kb & (NSTG - 1)) * 16 + 8);

        // ---- odd: consume kb+1 with A1; prefetch A(kb+2) ----
        if (kb + 8 < NKB) STAGE(kb + 8, true);
        if (kb + 2 < NKB) LDGA(A0, kb + 2);
        MB_WAIT(sb + ((kb + 1) & (NSTG - 1)) * 16, ((kb + 1) >> 3) & 1);
        LDB(Bf, kb + 1);
        DOMMA(A1, Bf);
        if (lane == 0) MB_ARRIVE(sb + ((kb + 1) & (NSTG - 1)) * 16 + 8);
    }

    __syncthreads();   // protect mbarriers/stages before C overlay

    // ---- epilogue: frags -> C[128][129] fp32, then fused neuron math ----
    float* C = (float*)smem;
#pragma unroll
    for (int mt = 0; mt < 4; mt++)
#pragma unroll
        for (int nt = 0; nt < 4; nt++) {
            const int r  = wm * 64 + mt * 16 + (lane >> 2);
            const int cc = wn * 32 + nt * 8 + (lane & 3) * 2;
            C[r * C_STRIDE + cc]           = acc[mt][nt][0];
            C[r * C_STRIDE + cc + 1]       = acc[mt][nt][1];
            C[(r + 8) * C_STRIDE + cc]     = acc[mt][nt][2];
            C[(r + 8) * C_STRIDE + cc + 1] = acc[mt][nt][3];
        }
    __syncthreads();

    // 2 threads per o-row: (row, half h of ds)
    const int row = tid & 127;
    const int h   = tid >> 7;
    const int o   = o0 + row;
    float td[4] = {0.f, 0.f, 0.f, 0.f};
    const float4* w4 = (const float4*)(w_syn + (size_t)o * 128 + h * 64);
#pragma unroll
    for (int j4 = 0; j4 < 16; j4++) {
        const float4 w = w4[j4];
        const int e = h * 64 + j4 * 4;
        td[j4 >> 2] += C[row * C_STRIDE + e]     * w.x
                     + C[row * C_STRIDE + e + 1] * w.y
                     + C[row * C_STRIDE + e + 2] * w.z
                     + C[row * C_STRIDE + e + 3] * w.w;
    }
    float sh = 0.f;
#pragma unroll
    for (int d = 0; d < 4; d++) {
        const int dd = h * 4 + d;
        sh += tanhf(td[d] + b_dend[o * 8 + dd]) * w_dend[o * 8 + dd];
    }
    float* spart = (float*)(smem + 128 * C_STRIDE * 4);
    spart[h * 128 + row] = sh;
    __syncthreads();
    if (tid < 128) {
        const float s = spart[tid] + spart[128 + tid] + b_soma[o0 + tid];
        out[b * NN + o0 + tid] = 1.0f / (1.0f + expf(-s));
    }
}

// ---------------------------------------------------------------------------
extern "C" void kernel_launch(void* const* d_in, const int* in_sizes, int n_in,
                              void* d_out, int out_size)
{
    const float* x      = (const float*)d_in[0];   // [B, N, D, S]
    const float* M      = (const float*)d_in[1];   // [N, N]
    const float* w_syn  = (const float*)d_in[2];   // [N, D, S]
    const float* b_dend = (const float*)d_in[3];   // [N, D]
    const float* w_dend = (const float*)d_in[4];   // [N, D]
    const float* b_soma = (const float*)d_in[5];   // [N]
    float* out          = (float*)d_out;           // [B, N]

    cudaFuncSetAttribute(gemm_neuron, cudaFuncAttributeMaxDynamicSharedMemorySize, SMEM_REQ);

    prep<<<dim3(64, 64), 256>>>(x, M);
    gemm_neuron<<<dim3(NN / 128, BB), 256, SMEM_REQ>>>(w_syn, b_dend, w_dend, b_soma, out);
}

// round 16
// speedup vs baseline: 1.1209x; 1.0881x over previous
#include <cuda_runtime.h>
#include <cuda_fp16.h>
#include <math.h>
#include <stdint.h>

// Problem constants: B=64, N=1024, D=8, S=16 -> DS=128, K=1024
#define NN    1024
#define BB    64
#define DS    128
#define KDIM  1024
#define NKB   (KDIM / 16)            // 64 k16-blocks
#define NSTG  8                      // pipeline stages
#define STGB  8192                   // bytes per stage: A 4KB + B 4KB (frag order)
#define C_STRIDE 129
#define SMEM_REQ (128 * C_STRIDE * 4 + 1024)   // 67072 (covers 1024 + 8*8192 = 66560)

__device__ __forceinline__ uint32_t smem_u32(const void* p) {
    uint32_t a;
    asm("{ .reg .u64 t; cvta.to.shared.u64 t, %1; cvt.u32.u64 %0, t; }" : "=r"(a) : "l"(p));
    return a;
}
__device__ __forceinline__ void cp16(uint32_t dst, const void* src) {
    asm volatile("cp.async.cg.shared.global [%0], [%1], 16;" :: "r"(dst), "l"(src) : "memory");
}
__device__ __forceinline__ void mma16816(float* c, const uint32_t* a, uint32_t b0, uint32_t b1) {
    asm volatile("mma.sync.aligned.m16n8k16.row.col.f32.f16.f16.f32 "
                 "{%0,%1,%2,%3}, {%4,%5,%6,%7}, {%8,%9}, {%0,%1,%2,%3};"
                 : "+f"(c[0]), "+f"(c[1]), "+f"(c[2]), "+f"(c[3])
                 : "r"(a[0]), "r"(a[1]), "r"(a[2]), "r"(a[3]), "r"(b0), "r"(b1));
}

#define MB_INIT(mbar, cnt) \
    asm volatile("mbarrier.init.shared.b64 [%0], %1;" :: "r"(mbar), "r"((uint32_t)(cnt)) : "memory")
#define MB_ARRIVE(mbar) \
    asm volatile("mbarrier.arrive.shared.b64 _, [%0];" :: "r"(mbar) : "memory")
// .noinc is load-bearing: without it each call bumps the pending count first
// (net-zero progress) and the barrier never completes (R11 deadlock).
#define CP_MB_ARRIVE(mbar) \
    asm volatile("cp.async.mbarrier.arrive.noinc.shared::cta.b64 [%0];" :: "r"(mbar) : "memory")
#define MB_WAIT(mbar, par) do {                                                \
    uint32_t _m = (mbar); uint32_t _p = (uint32_t)(par);                       \
    asm volatile("{\n\t.reg .pred P1;\n\t"                                     \
        "WL_%=:\n\t"                                                           \
        "mbarrier.try_wait.parity.acquire.cta.shared::cta.b64 P1, [%0], %1, 0x989680;\n\t" \
        "@P1 bra.uni WD_%=;\n\t"                                               \
        "bra.uni WL_%=;\n\t"                                                   \
        "WD_%=:\n\t}"                                                          \
        :: "r"(_m), "r"(_p) : "memory");                                       \
} while (0)

// ---------------- device scratch: FRAGMENT-ORDERED operands ----------------
// A frags: [row16 0..63][kb 0..63][lane 0..31][4 u32]   (2 MB)
// B frags: [b*8 + n16][kb][lane][4 u32]                (16 MB)
__device__ uint32_t g_Af[64 * NKB * 128];
__device__ uint32_t g_Xf[BB * 8 * NKB * 128];

// ---------------- prep: build fragment-ordered A and B ---------------------
// SX_STRIDE = 133 (odd): drain reads sx[k0*133+n]; k0*133 = k0*5 (mod 32)
// maps the 8 k0 values to 8 DISTINCT banks (<=2-way with the n offsets).
// The old 132 stride gave k0*4 (mod 32) -> only banks {0,8,16,24} = 4-way
// conflicts on every one of the 8 LDS per thread.
#define SX_STRIDE 133
__global__ void prep(const float* __restrict__ x, const float* __restrict__ M)
{
    const int tid = threadIdx.x;
    const int kb  = blockIdx.x;

    if (tid < 128) {
        const int row16 = blockIdx.y;
        const int lane = tid >> 2, reg = tid & 3;
        const int R = row16 * 16 + (lane >> 2) + (reg & 1) * 8;
        const int C = kb * 16 + (lane & 3) * 2 + ((reg >> 1) & 1) * 8;
        const float2 mv = *(const float2*)&M[(size_t)R * NN + C];
        const __half2 h = __floats2half2_rn(mv.x, mv.y);
        g_Af[((size_t)row16 * NKB + kb) * 128 + tid] = *(const uint32_t*)&h;
    }

    __shared__ float sx[16 * SX_STRIDE];
    const int b = blockIdx.y;
    const float* src = x + ((size_t)b * NN + kb * 16) * DS;
#pragma unroll
    for (int j = tid; j < 16 * 128; j += 256) {
        const int r = j >> 7, c = j & 127;
        sx[r * SX_STRIDE + c] = src[r * DS + c];
    }
    __syncthreads();

    uint32_t* dstB = g_Xf + ((size_t)(b * 8) * NKB + kb) * 128;
#pragma unroll
    for (int it = 0; it < 4; it++) {
        const int u = it * 256 + tid;
        const int n16 = u >> 7, tt = u & 127;
        const int lane = tt >> 2, reg = tt & 3;
        const int n  = n16 * 16 + (lane >> 2) + ((reg >> 1) & 1) * 8;
        const int k0 = (lane & 3) * 2 + (reg & 1) * 8;
        const __half2 h = __floats2half2_rn(sx[k0 * SX_STRIDE + n],
                                            sx[(k0 + 1) * SX_STRIDE + n]);
        dstB[(size_t)n16 * (NKB * 128) + tt] = *(const uint32_t*)&h;
    }
}

// ---------------- GEMM: 8-stage mbarrier cp.async pipeline (R13, at the ----
// mma.sync fp16 hardware floor: 1024 FLOP/cyc/SM -> ~60us; do not touch) ----
// Grid (8, 64). Block 256 = 8 warps (2 m x 4 n), warp m64n32.
__global__ void __launch_bounds__(256, 2) gemm_neuron(
    const float* __restrict__ w_syn,    // [N, 128]
    const float* __restrict__ b_dend,   // [N, 8]
    const float* __restrict__ w_dend,   // [N, 8]
    const float* __restrict__ b_soma,   // [N]
    float* __restrict__ out)            // [B, N]
{
    extern __shared__ char smem[];
    const uint32_t sb = smem_u32(smem);
    const int tid  = threadIdx.x;
    const int wid  = tid >> 5, lane = tid & 31;
    const int wm   = wid & 1;           // m-warp: 64 rows
    const int wn   = wid >> 1;          // n-warp: 32 cols
    const int o0   = blockIdx.x * 128;
    const int b    = blockIdx.y;

    if (tid == 0) {
#pragma unroll
        for (int s = 0; s < NSTG; s++) {
            MB_INIT(sb + s * 16,     256);   // full: 256 cp.async noinc arrivals
            MB_INIT(sb + s * 16 + 8, 8);     // empty: one arrive per warp
        }
    }
    __syncthreads();

    // staging role: threads 0..127 -> A tile (tt>>4), 128..255 -> B tile
    const int  isA = (tid < 128);
    const int  tt  = isA ? tid : tid - 128;
    const int  tile = isA ? (blockIdx.x * 8 + (tt >> 4)) : (b * 8 + (tt >> 4));
    const uint32_t* srcbase = (isA ? g_Af : g_Xf)
                            + ((size_t)tile * NKB) * 128 + (tt & 15) * 8;
    const uint32_t dstoff = 1024 + (isA ? 0 : 4096) + (tt >> 4) * 512 + (tt & 15) * 32;

#define STAGE(j, dowait) do {                                              \
    const int _s = (j) & (NSTG - 1);                                       \
    if (dowait) MB_WAIT(sb + _s * 16 + 8, (((j) >> 3) + 1) & 1);           \
    const uint32_t _d = sb + dstoff + _s * STGB;                           \
    const uint32_t* _src = srcbase + (size_t)(j) * 128;                    \
    cp16(_d,      _src);                                                   \
    cp16(_d + 16, _src + 4);                                               \
    CP_MB_ARRIVE(sb + _s * 16);                                            \
} while (0)

    // prologue: fill 7 stages (no waits needed, buffers virgin)
#pragma unroll
    for (int j = 0; j < NSTG - 1; j++) STAGE(j, false);

    float acc[4][4][4];
#pragma unroll
    for (int mt = 0; mt < 4; mt++)
#pragma unroll
        for (int nt = 0; nt < 4; nt++)
#pragma unroll
            for (int q = 0; q < 4; q++) acc[mt][nt][q] = 0.f;

    const uint32_t aoff = 1024 + wm * 4 * 512 + lane * 16;
    const uint32_t boff = 1024 + 4096 + wn * 2 * 512 + lane * 16;

#pragma unroll 2
    for (int kb = 0; kb < NKB; kb++) {
        if (kb + NSTG - 1 < NKB) STAGE(kb + NSTG - 1, true);

        const int s = kb & (NSTG - 1);
        MB_WAIT(sb + s * 16, (kb >> 3) & 1);

        const char* stg = smem + s * STGB;
        uint4 Af[4], Bf[2];
#pragma unroll
        for (int mt = 0; mt < 4; mt++)
            Af[mt] = *(const uint4*)(stg + aoff + mt * 512);
#pragma unroll
        for (int bt = 0; bt < 2; bt++)
            Bf[bt] = *(const uint4*)(stg + boff + bt * 512);

#pragma unroll
        for (int mt = 0; mt < 4; mt++)
#pragma unroll
            for (int bt = 0; bt < 2; bt++) {
                mma16816(acc[mt][bt * 2],     (const uint32_t*)&Af[mt], Bf[bt].x, Bf[bt].y);
                mma16816(acc[mt][bt * 2 + 1], (const uint32_t*)&Af[mt], Bf[bt].z, Bf[bt].w);
            }

        // warp-converged after mma.sync: one empty-arrive per warp
        if (lane == 0) MB_ARRIVE(sb + s * 16 + 8);
    }

    __syncthreads();   // protect mbarriers/stages before C overlay

    // ---- epilogue: frags -> C[128][129] fp32, then fused neuron math ----
    float* C = (float*)smem;
#pragma unroll
    for (int mt = 0; mt < 4; mt++)
#pragma unroll
        for (int nt = 0; nt < 4; nt++) {
            const int r  = wm * 64 + mt * 16 + (lane >> 2);
            const int cc = wn * 32 + nt * 8 + (lane & 3) * 2;
            C[r * C_STRIDE + cc]           = acc[mt][nt][0];
            C[r * C_STRIDE + cc + 1]       = acc[mt][nt][1];
            C[(r + 8) * C_STRIDE + cc]     = acc[mt][nt][2];
            C[(r + 8) * C_STRIDE + cc + 1] = acc[mt][nt][3];
        }
    __syncthreads();

    // 2 threads per o-row: (row, half h of ds)
    const int row = tid & 127;
    const int h   = tid >> 7;
    const int o   = o0 + row;
    float td[4] = {0.f, 0.f, 0.f, 0.f};
    const float4* w4 = (const float4*)(w_syn + (size_t)o * 128 + h * 64);
#pragma unroll
    for (int j4 = 0; j4 < 16; j4++) {
        const float4 w = w4[j4];
        const int e = h * 64 + j4 * 4;
        td[j4 >> 2] += C[row * C_STRIDE + e]     * w.x
                     + C[row * C_STRIDE + e + 1] * w.y
                     + C[row * C_STRIDE + e + 2] * w.z
                     + C[row * C_STRIDE + e + 3] * w.w;
    }
    float sh = 0.f;
#pragma unroll
    for (int d = 0; d < 4; d++) {
        const int dd = h * 4 + d;
        sh += tanhf(td[d] + b_dend[o * 8 + dd]) * w_dend[o * 8 + dd];
    }
    float* spart = (float*)(smem + 128 * C_STRIDE * 4);
    spart[h * 128 + row] = sh;
    __syncthreads();
    if (tid < 128) {
        const float s = spart[tid] + spart[128 + tid] + b_soma[o0 + tid];
        out[b * NN + o0 + tid] = 1.0f / (1.0f + expf(-s));
    }
}

// ---------------------------------------------------------------------------
extern "C" void kernel_launch(void* const* d_in, const int* in_sizes, int n_in,
                              void* d_out, int out_size)
{
    const float* x      = (const float*)d_in[0];   // [B, N, D, S]
    const float* M      = (const float*)d_in[1];   // [N, N]
    const float* w_syn  = (const float*)d_in[2];   // [N, D, S]
    const float* b_dend = (const float*)d_in[3];   // [N, D]
    const float* w_dend = (const float*)d_in[4];   // [N, D]
    const float* b_soma = (const float*)d_in[5];   // [N]
    float* out          = (float*)d_out;           // [B, N]

    cudaFuncSetAttribute(gemm_neuron, cudaFuncAttributeMaxDynamicSharedMemorySize, SMEM_REQ);

    prep<<<dim3(64, 64), 256>>>(x, M);
    gemm_neuron<<<dim3(NN / 128, BB), 256, SMEM_REQ>>>(w_syn, b_dend, w_dend, b_soma, out);
}

// round 17
// speedup vs baseline: 1.1547x; 1.0301x over previous
#include <cuda_runtime.h>
#include <cuda_fp16.h>
#include <math.h>
#include <stdint.h>

// Problem constants: B=64, N=1024, D=8, S=16 -> DS=128, K=1024
#define NN    1024
#define BB    64
#define DS    128
#define KDIM  1024
#define NKB   (KDIM / 16)            // 64 k16-blocks
#define C_STRIDE 129
#define SX_STRIDE 133                // odd stride: k0*133 = k0*5 (mod 32), conflict-free drain
#define SMEM_REQ (128 * C_STRIDE * 4 + 1024)   // 67072 (epilogue C; prep sx uses 8512B of it)

__device__ __forceinline__ void mma16816(float* c, const uint32_t* a, uint32_t b0, uint32_t b1) {
    asm volatile("mma.sync.aligned.m16n8k16.row.col.f32.f16.f16.f32 "
                 "{%0,%1,%2,%3}, {%4,%5,%6,%7}, {%8,%9}, {%0,%1,%2,%3};"
                 : "+f"(c[0]), "+f"(c[1]), "+f"(c[2]), "+f"(c[3])
                 : "r"(a[0]), "r"(a[1]), "r"(a[2]), "r"(a[3]), "r"(b0), "r"(b1));
}

// ---------------- device scratch: FRAGMENT-ORDERED operands ----------------
// A frags: [row16 0..63][kb 0..63][lane 0..31][4 u32]   (2 MB)
// B frags: [b*8 + n16][kb][lane][4 u32]                (16 MB)
__device__ uint32_t g_Af[64 * NKB * 128];
__device__ uint32_t g_Xf[BB * 8 * NKB * 128];
__device__ int      g_cnt[BB];            // per-batch prep-arrival counters

// ---------------- prepA: M -> fragment-ordered fp16 + zero counters --------
// 512 blocks x 256 threads; each thread produces 4 u32 of g_Af.
__global__ void prepA(const float* __restrict__ M)
{
    if (blockIdx.x == 0 && threadIdx.x < BB) g_cnt[threadIdx.x] = 0;
    const int gid = blockIdx.x * 256 + threadIdx.x;
#pragma unroll
    for (int j = 0; j < 4; j++) {
        const int idx   = gid * 4 + j;
        const int row16 = idx >> 13;
        const int kb    = (idx >> 7) & 63;
        const int tt    = idx & 127;
        const int lane  = tt >> 2, reg = tt & 3;
        const int R = row16 * 16 + (lane >> 2) + (reg & 1) * 8;
        const int C = kb * 16 + (lane & 3) * 2 + ((reg >> 1) & 1) * 8;
        const float2 mv = *(const float2*)&M[(size_t)R * NN + C];
        const __half2 h = __floats2half2_rn(mv.x, mv.y);
        g_Af[idx] = *(const uint32_t*)&h;
    }
}

// ---------------- fused: per-group B-prep + group barrier + R10 gemm -------
// Grid (8, 64): ox = o-tile AND kb-slice owner, b = batch.
// The 8 CTAs of batch b each prep kb in [8*ox, 8*ox+8) of g_Xf[b], arrive on
// g_cnt[b], spin to 8, then run the direct-LDG mainloop (R10 champion).
// Deadlock-free: groups are 8 contiguous linear block ids; wave-1 = 296 = 37
// full groups; remaining 216 CTAs all co-resident once wave 1 drains.
__global__ void __launch_bounds__(256, 2) gemm_neuron(
    const float* __restrict__ x,        // [B, N, 128]
    const float* __restrict__ w_syn,    // [N, 128]
    const float* __restrict__ b_dend,   // [N, 8]
    const float* __restrict__ w_dend,   // [N, 8]
    const float* __restrict__ b_soma,   // [N]
    float* __restrict__ out)            // [B, N]
{
    extern __shared__ char smem[];
    const int tid  = threadIdx.x;
    const int wid  = tid >> 5, lane = tid & 31;
    const int wm   = wid & 1;           // m-warp: 64 rows
    const int wn   = wid >> 1;          // n-warp: 32 cols (2 n16 tiles)
    const int ox   = blockIdx.x;
    const int b    = blockIdx.y;
    const int o0   = ox * 128;

    // ---- phase 1: prep this CTA's 8 kb-slabs of g_Xf[b] ----
    float* sx = (float*)smem;           // 16 x SX_STRIDE floats (8512 B)
    for (int kk = 0; kk < 8; kk++) {
        const int kb = ox * 8 + kk;
        const float* src = x + ((size_t)b * NN + kb * 16) * DS;
#pragma unroll
        for (int j = tid; j < 16 * 128; j += 256) {
            const int r = j >> 7, c = j & 127;
            sx[r * SX_STRIDE + c] = src[r * DS + c];
        }
        __syncthreads();
        uint32_t* dstB = g_Xf + ((size_t)(b * 8) * NKB + kb) * 128;
#pragma unroll
        for (int it = 0; it < 4; it++) {
            const int u = it * 256 + tid;
            const int n16 = u >> 7, tt = u & 127;
            const int fl = tt >> 2, reg = tt & 3;
            const int n  = n16 * 16 + (fl >> 2) + ((reg >> 1) & 1) * 8;
            const int k0 = (fl & 3) * 2 + (reg & 1) * 8;
            const __half2 h = __floats2half2_rn(sx[k0 * SX_STRIDE + n],
                                                sx[(k0 + 1) * SX_STRIDE + n]);
            dstB[(size_t)n16 * (NKB * 128) + tt] = *(const uint32_t*)&h;
        }
        __syncthreads();
    }
    __threadfence();                    // g_Xf writes visible to peer CTAs
    if (tid == 0) {
        atomicAdd(&g_cnt[b], 1);
        while (atomicAdd(&g_cnt[b], 0) < 8) __nanosleep(64);
    }
    __syncthreads();

    // ---- phase 2: R10 direct-LDG mainloop (at the mma.sync HW floor) ----
    const uint4* pa = (const uint4*)g_Af
                    + ((size_t)(ox * 8 + wm * 4) * NKB) * 32 + lane;
    const uint4* pb = (const uint4*)g_Xf
                    + ((size_t)(b * 8 + wn * 2) * NKB) * 32 + lane;
    // strides (uint4 units): mt/bt tile = NKB*32 = 2048, kb step = 32

    float acc[4][4][4];
#pragma unroll
    for (int mt = 0; mt < 4; mt++)
#pragma unroll
        for (int nt = 0; nt < 4; nt++)
#pragma unroll
            for (int q = 0; q < 4; q++) acc[mt][nt][q] = 0.f;

    uint4 A0[4], B0[2], A1[4], B1[2];

#define LDFR(Ar, Br, kb) do {                                              \
    _Pragma("unroll")                                                      \
    for (int mt = 0; mt < 4; mt++) Ar[mt] = pa[mt * 2048 + (kb) * 32];     \
    _Pragma("unroll")                                                      \
    for (int bt = 0; bt < 2; bt++) Br[bt] = pb[bt * 2048 + (kb) * 32];     \
} while (0)

#define DOMMA(Ar, Br) do {                                                 \
    _Pragma("unroll")                                                      \
    for (int mt = 0; mt < 4; mt++) {                                       \
        _Pragma("unroll")                                                  \
        for (int bt = 0; bt < 2; bt++) {                                   \
            mma16816(acc[mt][bt * 2],     (const uint32_t*)&Ar[mt],        \
                     Br[bt].x, Br[bt].y);                                  \
            mma16816(acc[mt][bt * 2 + 1], (const uint32_t*)&Ar[mt],        \
                     Br[bt].z, Br[bt].w);                                  \
        }                                                                  \
    }                                                                      \
} while (0)

    LDFR(A0, B0, 0);
#pragma unroll 4
    for (int kb = 0; kb < NKB; kb += 2) {
        LDFR(A1, B1, (kb + 1) & (NKB - 1));
        DOMMA(A0, B0);
        LDFR(A0, B0, (kb + 2) & (NKB - 1));   // last iter: harmless reload of 0
        DOMMA(A1, B1);
    }

    __syncthreads();   // prep sx / frag reads done before C overlay

    // ---- epilogue: frags -> C[128][129] fp32, then fused neuron math ----
    float* C = (float*)smem;
#pragma unroll
    for (int mt = 0; mt < 4; mt++)
#pragma unroll
        for (int nt = 0; nt < 4; nt++) {
            const int r  = wm * 64 + mt * 16 + (lane >> 2);
            const int cc = wn * 32 + nt * 8 + (lane & 3) * 2;
            C[r * C_STRIDE + cc]           = acc[mt][nt][0];
            C[r * C_STRIDE + cc + 1]       = acc[mt][nt][1];
            C[(r + 8) * C_STRIDE + cc]     = acc[mt][nt][2];
            C[(r + 8) * C_STRIDE + cc + 1] = acc[mt][nt][3];
        }
    __syncthreads();

    // 2 threads per o-row: (row, half h of ds)
    const int row = tid & 127;
    const int h   = tid >> 7;
    const int o   = o0 + row;
    float td[4] = {0.f, 0.f, 0.f, 0.f};
    const float4* w4 = (const float4*)(w_syn + (size_t)o * 128 + h * 64);
#pragma unroll
    for (int j4 = 0; j4 < 16; j4++) {
        const float4 w = w4[j4];
        const int e = h * 64 + j4 * 4;
        td[j4 >> 2] += C[row * C_STRIDE + e]     * w.x
                     + C[row * C_STRIDE + e + 1] * w.y
                     + C[row * C_STRIDE + e + 2] * w.z
                     + C[row * C_STRIDE + e + 3] * w.w;
    }
    float sh = 0.f;
#pragma unroll
    for (int d = 0; d < 4; d++) {
        const int dd = h * 4 + d;
        sh += tanhf(td[d] + b_dend[o * 8 + dd]) * w_dend[o * 8 + dd];
    }
    float* spart = (float*)(smem + 128 * C_STRIDE * 4);
    spart[h * 128 + row] = sh;
    __syncthreads();
    if (tid < 128) {
        const float s = spart[tid] + spart[128 + tid] + b_soma[o0 + tid];
        out[b * NN + o0 + tid] = 1.0f / (1.0f + expf(-s));
    }
}

// ---------------------------------------------------------------------------
extern "C" void kernel_launch(void* const* d_in, const int* in_sizes, int n_in,
                              void* d_out, int out_size)
{
    const float* x      = (const float*)d_in[0];   // [B, N, D, S]
    const float* M      = (const float*)d_in[1];   // [N, N]
    const float* w_syn  = (const float*)d_in[2];   // [N, D, S]
    const float* b_dend = (const float*)d_in[3];   // [N, D]
    const float* w_dend = (const float*)d_in[4];   // [N, D]
    const float* b_soma = (const float*)d_in[5];   // [N]
    float* out          = (float*)d_out;           // [B, N]

    cudaFuncSetAttribute(gemm_neuron, cudaFuncAttributeMaxDynamicSharedMemorySize, SMEM_REQ);

    prepA<<<512, 256>>>(M);
    gemm_neuron<<<dim3(NN / 128, BB), 256, SMEM_REQ>>>(
        x, w_syn, b_dend, w_dend, b_soma, out);
}